// round 6
// baseline (speedup 1.0000x reference)
#include <cuda_runtime.h>

#define N_NODES    100000
#define N_EDGES    3200000
#define NUM_GRAPHS 128
#define HID        64
#define IN_DIM     15
#define NBLK       ((N_NODES + 255) / 256)   // scan blocks
#define NPB        96                        // nodes per linear block

// ---------------- scratch (device globals; no allocation allowed) -----------
// hs: bf16x2 per (node, lane-pair). +1 zero pad row for OOB gather lanes.
__device__ __align__(16) unsigned g_hs[(N_NODES + 1) * 32];
__device__ __align__(16) float    g_aggA[N_NODES * HID];
__device__ __align__(16) float    g_aggB[N_NODES * HID];
__device__ int   g_csrc [N_EDGES];
__device__ int   g_edeg  [N_NODES];
__device__ int   g_pre   [N_NODES];
__device__ int   g_rowptr[N_NODES];
__device__ int   g_fill  [N_NODES];
__device__ int   g_bsum[NBLK];
__device__ int   g_boff[NBLK];
__device__ float g_dis[N_NODES];
__device__ float g_cnt[NUM_GRAPHS];
__device__ int   g_e32;
__device__ int   g_b32;

// ---------------- packed f32x2 helpers ---------------------------------------
__device__ __forceinline__ unsigned long long fma2(unsigned long long a,
                                                   unsigned long long b,
                                                   unsigned long long c) {
    unsigned long long d;
    asm("fma.rn.f32x2 %0, %1, %2, %3;" : "=l"(d) : "l"(a), "l"(b), "l"(c));
    return d;
}
__device__ __forceinline__ unsigned long long pack2(float x) {
    unsigned long long d;
    asm("mov.b64 %0, {%1, %1};" : "=l"(d) : "f"(x));
    return d;
}

// ---------------- init: zero degrees + pad row + dtype detection -------------
__global__ void gnn_init(const void* edges, const void* batch) {
    int v = blockIdx.x * blockDim.x + threadIdx.x;
    if (v < N_NODES) g_edeg[v] = 0;
    if (blockIdx.x == 0 && threadIdx.x < 32)
        g_hs[N_NODES * 32 + threadIdx.x] = 0u;
    if (blockIdx.x == gridDim.x - 1) {
        __shared__ int se, sb;
        if (threadIdx.x == 0) { se = 0; sb = 0; }
        __syncthreads();
        for (int i = threadIdx.x; i < 2048; i += 256) {
            long long vi = (long long)i * (N_EDGES / 2048);
            long long x = ((const long long*)edges)[vi];
            if (x < 0 || x >= N_NODES) { atomicOr(&se, 1); break; }
        }
        for (int i = threadIdx.x; i < 2048; i += 256) {
            long long vi = (long long)i * ((N_NODES / 2) / 2048);
            long long x = ((const long long*)batch)[vi];
            if (x < 0 || x >= NUM_GRAPHS) { atomicOr(&sb, 1); break; }
        }
        __syncthreads();
        if (threadIdx.x == 0) { g_e32 = se; g_b32 = sb; }
    }
}

__device__ __forceinline__ int batch_at(const void* batch, int v) {
    return g_b32 ? ((const int*)batch)[v] : (int)((const long long*)batch)[v];
}

// ---------------- degree count (4 edges/thread, int4 fast path) --------------
__global__ void gnn_deg_count(const void* __restrict__ edges) {
    int i = blockIdx.x * blockDim.x + threadIdx.x;
    if (i >= N_EDGES / 4) return;
    if (g_e32) {
        const int4* d4 = (const int4*)((const int*)edges + N_EDGES);
        int4 d = d4[i];
        atomicAdd(&g_edeg[d.x], 1);
        atomicAdd(&g_edeg[d.y], 1);
        atomicAdd(&g_edeg[d.z], 1);
        atomicAdd(&g_edeg[d.w], 1);
    } else {
        const long long* e = (const long long*)edges + N_EDGES;
#pragma unroll
        for (int t = 0; t < 4; t++)
            atomicAdd(&g_edeg[(int)e[i * 4 + t]], 1);
    }
}

// ---------------- scan1 (+ fused dis) -----------------------------------------
__global__ void gnn_scan1() {
    __shared__ int s[256];
    int t = threadIdx.x;
    int i = blockIdx.x * 256 + t;
    int dv = (i < N_NODES) ? g_edeg[i] : 0;
    s[t] = dv; __syncthreads();
    for (int off = 1; off < 256; off <<= 1) {
        int add = (t >= off) ? s[t - off] : 0;
        __syncthreads();
        s[t] += add;
        __syncthreads();
    }
    if (i < N_NODES) {
        g_pre[i] = s[t] - dv;
        g_dis[i] = rsqrtf((float)(dv + 1));   // + self loop
    }
    if (t == 255) g_bsum[blockIdx.x] = s[255];
}

__global__ void gnn_scan2() {
    __shared__ int s[512];
    int t = threadIdx.x;
    int v = (t < NBLK) ? g_bsum[t] : 0;
    s[t] = v; __syncthreads();
    for (int off = 1; off < 512; off <<= 1) {
        int add = (t >= off) ? s[t - off] : 0;
        __syncthreads();
        s[t] += add;
        __syncthreads();
    }
    if (t < NBLK) g_boff[t] = s[t] - v;
}

__global__ void gnn_scan3() {
    int i = blockIdx.x * blockDim.x + threadIdx.x;
    if (i < N_NODES) {
        g_rowptr[i] = g_pre[i] + g_boff[blockIdx.x];
        g_fill[i]   = 0;
    }
}

// ---------------- CSR fill (4 edges/thread) -----------------------------------
__global__ void gnn_csr_fill(const void* __restrict__ edges) {
    int i = blockIdx.x * blockDim.x + threadIdx.x;
    if (i >= N_EDGES / 4) return;
    int s0, s1, s2, s3, d0, d1, d2, d3;
    if (g_e32) {
        const int4* s4 = (const int4*)edges;
        const int4* d4 = (const int4*)((const int*)edges + N_EDGES);
        int4 s = s4[i]; int4 d = d4[i];
        s0 = s.x; s1 = s.y; s2 = s.z; s3 = s.w;
        d0 = d.x; d1 = d.y; d2 = d.z; d3 = d.w;
    } else {
        const long long* es = (const long long*)edges;
        s0 = (int)es[i*4]; s1 = (int)es[i*4+1]; s2 = (int)es[i*4+2]; s3 = (int)es[i*4+3];
        d0 = (int)es[N_EDGES+i*4]; d1 = (int)es[N_EDGES+i*4+1];
        d2 = (int)es[N_EDGES+i*4+2]; d3 = (int)es[N_EDGES+i*4+3];
    }
    g_csrc[g_rowptr[d0] + atomicAdd(&g_fill[d0], 1)] = s0;
    g_csrc[g_rowptr[d1] + atomicAdd(&g_fill[d1], 1)] = s1;
    g_csrc[g_rowptr[d2] + atomicAdd(&g_fill[d2], 1)] = s2;
    g_csrc[g_rowptr[d3] + atomicAdd(&g_fill[d3], 1)] = s3;
}

// ---------------- linear: hs[v] = bf16((relu(in+b) @ W) * dis[v]) ------------
// 256 threads, 96 nodes/block, 3 nodes/thread, 8 cols/thread, f32x2 packed FMA.
template <int K, bool PRE>
__global__ void __launch_bounds__(256) gnn_linear(const float* __restrict__ in,
                                                  const float* __restrict__ W,
                                                  const float* __restrict__ bias_prev,
                                                  unsigned* __restrict__ hs) {
    constexpr int SR = (K + 3) & ~3;   // row stride (16B-aligned rows)
    constexpr int K4 = K / 4;
    __shared__ float Wsh[K * HID];
    __shared__ float insh[NPB * SR];
    const int tid  = threadIdx.x;
    const int base = blockIdx.x * NPB;

    for (int i = tid; i < K * HID; i += 256) Wsh[i] = W[i];
    for (int i = tid; i < NPB * K; i += 256) {
        int n = i / K;
        int k = i - n * K;
        int v = base + n;
        float val = 0.0f;
        if (v < N_NODES) {
            val = in[v * K + k];
            if (PRE) val = fmaxf(val + bias_prev[k], 0.0f);
        }
        insh[n * SR + k] = val;
    }
    __syncthreads();

    const int ng = tid >> 3;          // 0..31, 3 nodes each
    const int cb = (tid & 7) * 8;     // col block (8 cols = 4 packed pairs)
    unsigned long long accp[3][4];
#pragma unroll
    for (int i = 0; i < 3; i++)
#pragma unroll
        for (int j = 0; j < 4; j++) accp[i][j] = 0ull;

#pragma unroll
    for (int k4 = 0; k4 < K4; k4++) {
        float4 a0 = *(const float4*)&insh[(ng * 3 + 0) * SR + k4 * 4];
        float4 a1 = *(const float4*)&insh[(ng * 3 + 1) * SR + k4 * 4];
        float4 a2 = *(const float4*)&insh[(ng * 3 + 2) * SR + k4 * 4];
#pragma unroll
        for (int t = 0; t < 4; t++) {
            int k = k4 * 4 + t;
            ulonglong2 w0 = *(const ulonglong2*)&Wsh[k * HID + cb];
            ulonglong2 w1 = *(const ulonglong2*)&Wsh[k * HID + cb + 4];
            float av0 = (t == 0) ? a0.x : (t == 1) ? a0.y : (t == 2) ? a0.z : a0.w;
            float av1 = (t == 0) ? a1.x : (t == 1) ? a1.y : (t == 2) ? a1.z : a1.w;
            float av2 = (t == 0) ? a2.x : (t == 1) ? a2.y : (t == 2) ? a2.z : a2.w;
            unsigned long long p0 = pack2(av0), p1 = pack2(av1), p2 = pack2(av2);
            accp[0][0] = fma2(p0, w0.x, accp[0][0]);
            accp[0][1] = fma2(p0, w0.y, accp[0][1]);
            accp[0][2] = fma2(p0, w1.x, accp[0][2]);
            accp[0][3] = fma2(p0, w1.y, accp[0][3]);
            accp[1][0] = fma2(p1, w0.x, accp[1][0]);
            accp[1][1] = fma2(p1, w0.y, accp[1][1]);
            accp[1][2] = fma2(p1, w1.x, accp[1][2]);
            accp[1][3] = fma2(p1, w1.y, accp[1][3]);
            accp[2][0] = fma2(p2, w0.x, accp[2][0]);
            accp[2][1] = fma2(p2, w0.y, accp[2][1]);
            accp[2][2] = fma2(p2, w1.x, accp[2][2]);
            accp[2][3] = fma2(p2, w1.y, accp[2][3]);
        }
    }
#pragma unroll
    for (int k = K4 * 4; k < K; k++) {   // K tail (K=15)
        ulonglong2 w0 = *(const ulonglong2*)&Wsh[k * HID + cb];
        ulonglong2 w1 = *(const ulonglong2*)&Wsh[k * HID + cb + 4];
#pragma unroll
        for (int i = 0; i < 3; i++) {
            unsigned long long p = pack2(insh[(ng * 3 + i) * SR + k]);
            accp[i][0] = fma2(p, w0.x, accp[i][0]);
            accp[i][1] = fma2(p, w0.y, accp[i][1]);
            accp[i][2] = fma2(p, w1.x, accp[i][2]);
            accp[i][3] = fma2(p, w1.y, accp[i][3]);
        }
    }

#pragma unroll
    for (int i = 0; i < 3; i++) {
        int v = base + ng * 3 + i;
        if (v < N_NODES) {
            float ds = g_dis[v];
#pragma unroll
            for (int j = 0; j < 4; j++) {
                unsigned long long p = accp[i][j];
                float fl = __uint_as_float((unsigned)(p & 0xffffffffull)) * ds;
                float fh = __uint_as_float((unsigned)(p >> 32)) * ds;
                unsigned r;
                asm("cvt.rn.bf16x2.f32 %0, %1, %2;" : "=r"(r) : "f"(fh), "f"(fl));
                hs[v * 32 + (cb >> 1) + j] = r;
            }
        }
    }
}

// ---------------- gather: agg[v] = dis[v] * (sum_e hs[src] + hs[v]) ----------
// One warp per node, lane owns 2 cols (bf16x2). Warp-uniform index loads
// (no shuffles); chunks of 8 with zero-pad-row fallback. FINAL fuses
// bias+relu+mean-pool reduction.
template <bool FINAL>
__global__ void __launch_bounds__(256) gnn_gather(const unsigned* __restrict__ hs,
                                                  float2* __restrict__ agg2,
                                                  const float2* __restrict__ bias2,
                                                  const void* __restrict__ batch,
                                                  float* __restrict__ out) {
    int warp = (blockIdx.x * blockDim.x + threadIdx.x) >> 5;
    int lane = threadIdx.x & 31;
    if (warp >= N_NODES) return;
    const int v   = warp;
    const int beg = g_rowptr[v];
    const int end = beg + g_edeg[v];

    unsigned h = hs[v * 32 + lane];   // self term
    float ax = __uint_as_float(h << 16);
    float ay = __uint_as_float(h & 0xffff0000u);

    for (int j = beg; j < end; j += 8) {
#pragma unroll
        for (int t = 0; t < 8; t++) {
            int jj = j + t;
            int s = N_NODES;                 // pad row (zeros)
            if (jj < end) s = g_csrc[jj];    // warp-uniform broadcast load
            unsigned hh = hs[s * 32 + lane];
            ax += __uint_as_float(hh << 16);
            ay += __uint_as_float(hh & 0xffff0000u);
        }
    }
    float ds = g_dis[v];
    ax *= ds; ay *= ds;

    if (!FINAL) {
        agg2[v * 32 + lane] = make_float2(ax, ay);
    } else {
        int g = batch_at(batch, v);
        float2 b = bias2[lane];
        ax = fmaxf(ax + b.x, 0.0f);
        ay = fmaxf(ay + b.y, 0.0f);
        float* p = &out[g * HID + lane * 2];
        asm volatile("red.global.add.f32 [%0], %1;" :: "l"(p),     "f"(ax) : "memory");
        asm volatile("red.global.add.f32 [%0], %1;" :: "l"(p + 1), "f"(ay) : "memory");
        if (lane == 0) atomicAdd(&g_cnt[g], 1.0f);
    }
}

// ---------------- pooling epilogue -------------------------------------------
__global__ void gnn_zero_out(float* __restrict__ out) {
    int i = blockIdx.x * blockDim.x + threadIdx.x;
    if (i < NUM_GRAPHS * HID) out[i] = 0.0f;
    if (i < NUM_GRAPHS) g_cnt[i] = 0.0f;
}

__global__ void gnn_div(float* __restrict__ out) {
    int i = blockIdx.x * blockDim.x + threadIdx.x;
    if (i < NUM_GRAPHS * HID) {
        int g = i >> 6;
        out[i] /= fmaxf(g_cnt[g], 1.0f);
    }
}

// ---------------- host -------------------------------------------------------
extern "C" void kernel_launch(void* const* d_in, const int* in_sizes, int n_in,
                              void* d_out, int out_size) {
    const float* x     = (const float*)d_in[0];
    const float* w1    = (const float*)d_in[1];
    const float* b1    = (const float*)d_in[2];
    const float* w2    = (const float*)d_in[3];
    const float* b2    = (const float*)d_in[4];
    const float* w3    = (const float*)d_in[5];
    const float* b3    = (const float*)d_in[6];
    const float* w4    = (const float*)d_in[7];
    const float* b4    = (const float*)d_in[8];
    const void*  edges = d_in[9];
    const void*  batch = d_in[10];
    float* out = (float*)d_out;

    void *p_hs, *p_aggA, *p_aggB;
    cudaGetSymbolAddress(&p_hs,   g_hs);
    cudaGetSymbolAddress(&p_aggA, g_aggA);
    cudaGetSymbolAddress(&p_aggB, g_aggB);
    unsigned* hs   = (unsigned*)p_hs;
    float*    aggA = (float*)p_aggA;
    float*    aggB = (float*)p_aggB;

    const int TB = 256;
    const int nodeB  = (N_NODES + TB - 1) / TB;
    const int edge4B = (N_EDGES / 4 + TB - 1) / TB;

    gnn_init     <<<nodeB, TB>>>(edges, batch);
    gnn_deg_count<<<edge4B, TB>>>(edges);
    gnn_scan1    <<<NBLK, 256>>>();
    gnn_scan2    <<<1, 512>>>();
    gnn_scan3    <<<NBLK, 256>>>();
    gnn_csr_fill <<<edge4B, TB>>>(edges);

    const int linB = (N_NODES + NPB - 1) / NPB;
    const int gatB = (N_NODES * 32 + TB - 1) / TB;

    // layer 1
    gnn_linear<IN_DIM, false><<<linB, TB>>>(x, w1, nullptr, hs);
    gnn_gather<false><<<gatB, TB>>>(hs, (float2*)aggA, nullptr, nullptr, nullptr);
    // layer 2
    gnn_linear<HID, true><<<linB, TB>>>(aggA, w2, b1, hs);
    gnn_gather<false><<<gatB, TB>>>(hs, (float2*)aggB, nullptr, nullptr, nullptr);
    // layer 3
    gnn_linear<HID, true><<<linB, TB>>>(aggB, w3, b2, hs);
    gnn_gather<false><<<gatB, TB>>>(hs, (float2*)aggA, nullptr, nullptr, nullptr);
    // layer 4 + fused bias/relu/mean-pool
    gnn_linear<HID, true><<<linB, TB>>>(aggA, w4, b3, hs);
    gnn_zero_out<<<(NUM_GRAPHS * HID + TB - 1) / TB, TB>>>(out);
    gnn_gather<true><<<gatB, TB>>>(hs, nullptr, (const float2*)b4, batch, out);
    gnn_div<<<(NUM_GRAPHS * HID + TB - 1) / TB, TB>>>(out);
}